// round 8
// baseline (speedup 1.0000x reference)
#include <cuda_runtime.h>
#include <cuda_fp16.h>

// Problem constants
#define Bsz  2
#define Cc   64
#define Hh   128
#define Ww   256
#define HG   122880          // grid rows = L*KH
#define LOUT 40960           // output rows after stride-3 depthwise
#define TL   8               // output rows per block (sampler)
#define NR   (3*TL + 2)      // local sampled rows incl. +/-1 halo  (26)
#define NP   (NR * 3)        // local sampled points (78)
#define NP_PAD 96            // multiple of 32 for uniform warp trips

__device__ __half g_xT[Bsz * Hh * Ww * Cc];        // x as [B,H,W,C] fp16
__device__ float  g_z[Bsz * LOUT * Cc];            // depthwise output [b*l][c]

// ---------------------------------------------------------------------------
// Kernel 1: NCHW fp32 -> NHWC fp16 transpose of x.
// ---------------------------------------------------------------------------
__global__ void transpose_k(const float* __restrict__ x) {
    __shared__ float tile[32][33];
    int w0 = blockIdx.x * 32;
    int c0 = blockIdx.y * 32;
    int bh = blockIdx.z;
    int b  = bh >> 7;          // H = 128
    int h  = bh & 127;
    int tx = threadIdx.x, ty = threadIdx.y;
#pragma unroll
    for (int i = 0; i < 4; i++) {
        int c = c0 + ty + i * 8;
        tile[ty + i * 8][tx] = x[((b * Cc + c) * Hh + h) * Ww + w0 + tx];
    }
    __syncthreads();
#pragma unroll
    for (int i = 0; i < 4; i++) {
        int w = w0 + ty + i * 8;
        g_xT[((size_t)(b * Hh + h) * Ww + w) * Cc + c0 + tx] =
            __float2half_rn(tile[tx][ty + i * 8]);
    }
}

// ---------------------------------------------------------------------------
// Kernel 2: grid_sample + spatial attention + depthwise(s=3) -> g_z
// grid: (LOUT/TL, B), block 128. ~12 KB smem -> many independent blocks/SM.
// ---------------------------------------------------------------------------
__global__ __launch_bounds__(128) void sample_k(
    const float* __restrict__ grid,
    const float* __restrict__ sa_w, const float* __restrict__ sa_b,
    const float* __restrict__ dw_w, const float* __restrict__ dw_b)
{
    __shared__ __align__(16) __half2 v_sm2[NP * 32];  // 9984 B sampled vecs
    __shared__ __align__(16) float4 cw_sm[NP_PAD];    // 1536 B bilinear wts
    __shared__ int cxy_sm[NP_PAD];                    //  384 B packed (x0,y0)
    __shared__ float savg[NP];
    __shared__ float smax_[NP];
    __shared__ float m_att[TL * 3 * 3];               // (1 + sigmoid) gates
    __shared__ float dw_sm[64 * 9];

    const int t  = threadIdx.x;
    const int b  = blockIdx.y;
    const int l0 = blockIdx.x * TL;
    const __half* __restrict__ xb = g_xT + (size_t)b * (Hh * Ww * Cc);

    // ---- Stage 0: dw weights + per-point coordinate precompute -------------
    for (int i = t; i < 576; i += 128)
        dw_sm[i] = dw_w[i];

    if (t < NP_PAD) {
        float4 w4 = make_float4(0.f, 0.f, 0.f, 0.f);
        int x0 = -30000, y0 = -30000;
        if (t < NP) {
            int gidx = (3 * l0 - 1) * 3 + t;          // linear grid point index
            if (gidx >= 0 && gidx < HG * 3) {
                float2 g2 = __ldg((const float2*)grid + gidx);
                float gx = (g2.x + 1.0f) * 128.0f - 0.5f;   // W/2
                float gy = (g2.y + 1.0f) * 64.0f  - 0.5f;   // H/2
                float x0f = floorf(gx), y0f = floorf(gy);
                float wx = gx - x0f, wy = gy - y0f;
                x0 = (int)x0f; y0 = (int)y0f;
                w4.x = (1.f - wx) * (1.f - wy);   // w00
                w4.y = wx * (1.f - wy);           // w10
                w4.z = (1.f - wx) * wy;           // w01
                w4.w = wx * wy;                   // w11
            }
        }
        cw_sm[t] = w4;
        cxy_sm[t] = (y0 << 16) | (x0 & 0xFFFF);
    }
    __syncthreads();

    // ---- Stage 1: bilinear gather, 8 lanes/point, 8 channels/lane ----------
    const int grp  = t >> 3;      // 0..15
    const int lane = t & 7;
    const int co   = lane * 8;    // channel offset (halves)

    for (int p = grp; p < NP_PAD; p += 16) {   // 6 uniform trips
        const bool active = (p < NP);
        float acc[8];
#pragma unroll
        for (int k = 0; k < 8; k++) acc[k] = 0.f;
        if (active) {
            float4 w4 = cw_sm[p];
            int pk = cxy_sm[p];
            int x0 = (int)(short)(pk & 0xFFFF);
            int y0 = pk >> 16;
            bool vx0 = (unsigned)x0       < (unsigned)Ww;
            bool vx1 = (unsigned)(x0 + 1) < (unsigned)Ww;
            bool vy0 = (unsigned)y0       < (unsigned)Hh;
            bool vy1 = (unsigned)(y0 + 1) < (unsigned)Hh;
            const __half* r0 = xb + (size_t)y0 * (Ww * 64) + co;
            const __half* r1 = r0 + (Ww * 64);
#pragma unroll
            for (int tap = 0; tap < 4; tap++) {
                bool v = (tap == 0) ? (vy0 && vx0) : (tap == 1) ? (vy0 && vx1)
                       : (tap == 2) ? (vy1 && vx0) : (vy1 && vx1);
                if (v) {
                    const __half* src = (tap < 2 ? r0 : r1) + ((tap & 1) ? (x0 + 1) : x0) * 64;
                    float w = (tap == 0) ? w4.x : (tap == 1) ? w4.y
                            : (tap == 2) ? w4.z : w4.w;
                    uint4 u = *(const uint4*)src;
                    float2 f0 = __half22float2(*(__half2*)&u.x);
                    float2 f1 = __half22float2(*(__half2*)&u.y);
                    float2 f2 = __half22float2(*(__half2*)&u.z);
                    float2 f3 = __half22float2(*(__half2*)&u.w);
                    acc[0] = fmaf(w, f0.x, acc[0]); acc[1] = fmaf(w, f0.y, acc[1]);
                    acc[2] = fmaf(w, f1.x, acc[2]); acc[3] = fmaf(w, f1.y, acc[3]);
                    acc[4] = fmaf(w, f2.x, acc[4]); acc[5] = fmaf(w, f2.y, acc[5]);
                    acc[6] = fmaf(w, f3.x, acc[6]); acc[7] = fmaf(w, f3.y, acc[7]);
                }
            }
        }
        // channel avg / max: local 8 then across the 8-lane group
        float sum = 0.f, mx = -3.0e38f;
#pragma unroll
        for (int k = 0; k < 8; k++) { sum += acc[k]; mx = fmaxf(mx, acc[k]); }
#pragma unroll
        for (int off = 4; off; off >>= 1) {
            sum += __shfl_xor_sync(0xFFFFFFFFu, sum, off);
            mx = fmaxf(mx, __shfl_xor_sync(0xFFFFFFFFu, mx, off));
        }
        if (active) {
            __half2 hv[4];
#pragma unroll
            for (int k = 0; k < 4; k++)
                hv[k] = __floats2half2_rn(acc[2*k], acc[2*k+1]);
            *(uint4*)&v_sm2[p * 32 + lane * 4] = *(uint4*)hv;
            if (lane == 0) { savg[p] = sum * (1.0f / 64.0f); smax_[p] = mx; }
        }
    }
    __syncthreads();

    // ---- Stage 2: spatial attention gates ----------------------------------
    if (t < TL * 3 * 3) {
        int ra = t / 3, kw = t - ra * 3;   // interior row ra -> v-row ra+1
        float acc = __ldg(sa_b);
#pragma unroll
        for (int kh = 0; kh < 3; kh++) {
            int rr = ra + kh;
#pragma unroll
            for (int k2 = 0; k2 < 3; k2++) {
                int cc = kw + k2 - 1;
                if (cc >= 0 && cc < 3) {
                    int p = rr * 3 + cc;
                    acc += __ldg(&sa_w[kh * 3 + k2])     * savg[p]
                         + __ldg(&sa_w[9 + kh * 3 + k2]) * smax_[p];
                }
            }
        }
        m_att[t] = 1.0f + 1.0f / (1.0f + __expf(-acc));
    }
    __syncthreads();

    // ---- Stage 3: depthwise 3x3, write z to global (coalesced 256B rows) ---
    {
        int c2 = t & 31;           // half2 channel pair (2 channels)
        int lg = t >> 5;           // 0..3
        int cA = 2 * c2, cB = 2 * c2 + 1;
        float dwA[9], dwB[9];
#pragma unroll
        for (int k = 0; k < 9; k++) { dwA[k] = dw_sm[cA * 9 + k]; dwB[k] = dw_sm[cB * 9 + k]; }
        float dbA = __ldg(&dw_b[cA]), dbB = __ldg(&dw_b[cB]);
#pragma unroll
        for (int li = 0; li < 2; li++) {
            int l = lg + li * 4;
            float a0 = dbA, a1 = dbB;
#pragma unroll
            for (int kh = 0; kh < 3; kh++)
#pragma unroll
                for (int kw = 0; kw < 3; kw++) {
                    int ra = 3 * l + kh;
                    float g = m_att[ra * 3 + kw];
                    float2 v = __half22float2(v_sm2[((ra + 1) * 3 + kw) * 32 + c2]);
                    a0 = fmaf(dwA[kh * 3 + kw] * g, v.x, a0);
                    a1 = fmaf(dwB[kh * 3 + kw] * g, v.y, a1);
                }
            *(float2*)&g_z[((size_t)b * LOUT + l0 + l) * 64 + cA] = make_float2(a0, a1);
        }
    }
}

// ---------------------------------------------------------------------------
// Kernel 3: pointwise 64x64 GEMM: out[b,o,l] = sum_c pw[o,c] * z[b,l,c] + pb.
// grid: (Bsz*LOUT/64), block 256. Tile 64o x 64l, thread 4o x 4l, k-major smem.
// ---------------------------------------------------------------------------
__global__ __launch_bounds__(256) void pw_k(
    const float* __restrict__ pw_w, const float* __restrict__ pw_b,
    float* __restrict__ out)
{
    __shared__ __align__(16) float zs[64][68];   // [c][l]
    __shared__ __align__(16) float pws[64][68];  // [c][o]

    const int t   = threadIdx.x;
    const int bl0 = blockIdx.x * 64;             // flattened (b*LOUT + l) tile base
    const int b   = bl0 / LOUT;                  // tiles never cross batch
    const int lbase = bl0 - b * LOUT;

    // Load pw transposed to [c][o]
    for (int i = t * 4; i < 4096; i += 1024) {
        float4 v = *(const float4*)&pw_w[i];
        int o = i >> 6, c = i & 63;
        pws[c + 0][o] = v.x; pws[c + 1][o] = v.y;
        pws[c + 2][o] = v.z; pws[c + 3][o] = v.w;
    }
    // Load z tile transposed to [c][l]
    const float* zg = g_z + (size_t)bl0 * 64;
    for (int i = t * 4; i < 4096; i += 1024) {
        float4 v = *(const float4*)&zg[i];
        int l = i >> 6, c = i & 63;
        zs[c + 0][l] = v.x; zs[c + 1][l] = v.y;
        zs[c + 2][l] = v.z; zs[c + 3][l] = v.w;
    }
    __syncthreads();

    const int tx = t & 15, ty = t >> 4;
    const int o0 = tx * 4, lt = ty * 4;

    float acc[4][4];
#pragma unroll
    for (int i = 0; i < 4; i++) {
        float pb = __ldg(&pw_b[o0 + i]);
#pragma unroll
        for (int j = 0; j < 4; j++) acc[i][j] = pb;
    }

#pragma unroll 8
    for (int k = 0; k < 64; k++) {
        float4 a  = *(const float4*)&pws[k][o0];
        float4 zv = *(const float4*)&zs[k][lt];
        acc[0][0] = fmaf(a.x, zv.x, acc[0][0]); acc[0][1] = fmaf(a.x, zv.y, acc[0][1]);
        acc[0][2] = fmaf(a.x, zv.z, acc[0][2]); acc[0][3] = fmaf(a.x, zv.w, acc[0][3]);
        acc[1][0] = fmaf(a.y, zv.x, acc[1][0]); acc[1][1] = fmaf(a.y, zv.y, acc[1][1]);
        acc[1][2] = fmaf(a.y, zv.z, acc[1][2]); acc[1][3] = fmaf(a.y, zv.w, acc[1][3]);
        acc[2][0] = fmaf(a.z, zv.x, acc[2][0]); acc[2][1] = fmaf(a.z, zv.y, acc[2][1]);
        acc[2][2] = fmaf(a.z, zv.z, acc[2][2]); acc[2][3] = fmaf(a.z, zv.w, acc[2][3]);
        acc[3][0] = fmaf(a.w, zv.x, acc[3][0]); acc[3][1] = fmaf(a.w, zv.y, acc[3][1]);
        acc[3][2] = fmaf(a.w, zv.z, acc[3][2]); acc[3][3] = fmaf(a.w, zv.w, acc[3][3]);
    }

#pragma unroll
    for (int i = 0; i < 4; i++) {
        float4 r = make_float4(acc[i][0], acc[i][1], acc[i][2], acc[i][3]);
        *(float4*)&out[((size_t)(b * 64 + o0 + i)) * LOUT + lbase + lt] = r;
    }
}

// ---------------------------------------------------------------------------
extern "C" void kernel_launch(void* const* d_in, const int* in_sizes, int n_in,
                              void* d_out, int out_size) {
    (void)in_sizes; (void)n_in; (void)out_size;
    const float* x    = (const float*)d_in[0];
    const float* grid = (const float*)d_in[1];
    const float* sa_w = (const float*)d_in[2];
    const float* sa_b = (const float*)d_in[3];
    const float* dw_w = (const float*)d_in[4];
    const float* dw_b = (const float*)d_in[5];
    const float* pw_w = (const float*)d_in[6];
    const float* pw_b = (const float*)d_in[7];
    float* out = (float*)d_out;

    dim3 tb(32, 8);
    dim3 tg(Ww / 32, Cc / 32, Bsz * Hh);
    transpose_k<<<tg, tb>>>(x);

    dim3 sg(LOUT / TL, Bsz);
    sample_k<<<sg, 128>>>(grid, sa_w, sa_b, dw_w, dw_b);

    pw_k<<<(Bsz * LOUT) / 64, 256>>>(pw_w, pw_b, out);
}

// round 10
// speedup vs baseline: 1.0963x; 1.0963x over previous
#include <cuda_runtime.h>
#include <cuda_fp16.h>

// Problem constants
#define Bsz  2
#define Cc   64
#define Hh   128
#define Ww   256
#define HG   122880          // grid rows = L*KH
#define LOUT 40960           // output rows after stride-3 depthwise
#define TL   16              // output rows per block (sampler)
#define NR   (3*TL + 2)      // local sampled rows incl. +/-1 halo  (50)
#define NP   (NR * 3)        // local sampled points (150)
#define NP_PAD 160           // padded for coord precompute
#define VROW 36              // v_sm2 row pitch in half2 (144B: aligned + conflict-free)

__device__ __half g_xT[Bsz * Hh * Ww * Cc];        // x as [B,H,W,C] fp16
__device__ float  g_z[Bsz * LOUT * Cc];            // depthwise output [b*l][c]

// ---------------------------------------------------------------------------
// Kernel 1: NCHW fp32 -> NHWC fp16 transpose of x.
// ---------------------------------------------------------------------------
__global__ void transpose_k(const float* __restrict__ x) {
    __shared__ float tile[32][33];
    int w0 = blockIdx.x * 32;
    int c0 = blockIdx.y * 32;
    int bh = blockIdx.z;
    int b  = bh >> 7;          // H = 128
    int h  = bh & 127;
    int tx = threadIdx.x, ty = threadIdx.y;
#pragma unroll
    for (int i = 0; i < 4; i++) {
        int c = c0 + ty + i * 8;
        tile[ty + i * 8][tx] = x[((b * Cc + c) * Hh + h) * Ww + w0 + tx];
    }
    __syncthreads();
#pragma unroll
    for (int i = 0; i < 4; i++) {
        int w = w0 + ty + i * 8;
        g_xT[((size_t)(b * Hh + h) * Ww + w) * Cc + c0 + tx] =
            __float2half_rn(tile[tx][ty + i * 8]);
    }
}

// ---------------------------------------------------------------------------
// Kernel 2: grid_sample + spatial attention + depthwise(s=3) -> g_z
// grid: (LOUT/TL, B), block 256.
// ---------------------------------------------------------------------------
__global__ __launch_bounds__(256) void sample_k(
    const float* __restrict__ grid,
    const float* __restrict__ sa_w, const float* __restrict__ sa_b,
    const float* __restrict__ dw_w, const float* __restrict__ dw_b)
{
    __shared__ __align__(16) __half2 v_sm2[NP * VROW]; // 21600 B sampled vecs
    __shared__ __align__(16) float4 cw_sm[NP_PAD];     //  2560 B bilinear wts
    __shared__ int cxy_sm[NP_PAD];                     //   640 B packed (x0,y0)
    __shared__ float savg[NP];
    __shared__ float smax_[NP];
    __shared__ float m_att[TL * 3 * 3];                // (1 + sigmoid) gates
    __shared__ float dw_sm[64 * 9];

    const int t  = threadIdx.x;
    const int b  = blockIdx.y;
    const int l0 = blockIdx.x * TL;
    const __half* __restrict__ xb = g_xT + (size_t)b * (Hh * Ww * Cc);

    // ---- Stage 0: dw weights + per-point coordinate precompute -------------
    for (int i = t; i < 576; i += 256)
        dw_sm[i] = dw_w[i];

    if (t < NP_PAD) {
        float4 w4 = make_float4(0.f, 0.f, 0.f, 0.f);
        int x0 = -30000, y0 = -30000;
        if (t < NP) {
            int gidx = (3 * l0 - 1) * 3 + t;          // linear grid point index
            if (gidx >= 0 && gidx < HG * 3) {
                float2 g2 = __ldg((const float2*)grid + gidx);
                float gx = (g2.x + 1.0f) * 128.0f - 0.5f;   // W/2
                float gy = (g2.y + 1.0f) * 64.0f  - 0.5f;   // H/2
                float x0f = floorf(gx), y0f = floorf(gy);
                float wx = gx - x0f, wy = gy - y0f;
                x0 = (int)x0f; y0 = (int)y0f;
                w4.x = (1.f - wx) * (1.f - wy);   // w00
                w4.y = wx * (1.f - wy);           // w10
                w4.z = (1.f - wx) * wy;           // w01
                w4.w = wx * wy;                   // w11
            }
        }
        cw_sm[t] = w4;
        cxy_sm[t] = (y0 << 16) | (x0 & 0xFFFF);
    }
    __syncthreads();

    // ---- Stage 1: bilinear gather, 8 lanes/point, 8 channels/lane ----------
    // No cross-lane ops inside the loop: short dependency chain, pipelinable.
    const int grp  = t >> 3;      // 0..31
    const int lane = t & 7;
    const int co   = lane * 8;    // channel offset (halves)

    for (int p = grp; p < NP; p += 32) {
        float acc[8];
#pragma unroll
        for (int k = 0; k < 8; k++) acc[k] = 0.f;
        float4 w4 = cw_sm[p];
        int pk = cxy_sm[p];
        int x0 = (int)(short)(pk & 0xFFFF);
        int y0 = pk >> 16;
        bool vx0 = (unsigned)x0       < (unsigned)Ww;
        bool vx1 = (unsigned)(x0 + 1) < (unsigned)Ww;
        bool vy0 = (unsigned)y0       < (unsigned)Hh;
        bool vy1 = (unsigned)(y0 + 1) < (unsigned)Hh;
        const __half* r0 = xb + (size_t)y0 * (Ww * 64) + co;
        const __half* r1 = r0 + (Ww * 64);
#pragma unroll
        for (int tap = 0; tap < 4; tap++) {
            bool v = (tap == 0) ? (vy0 && vx0) : (tap == 1) ? (vy0 && vx1)
                   : (tap == 2) ? (vy1 && vx0) : (vy1 && vx1);
            if (v) {
                const __half* src = (tap < 2 ? r0 : r1) + ((tap & 1) ? (x0 + 1) : x0) * 64;
                float w = (tap == 0) ? w4.x : (tap == 1) ? w4.y
                        : (tap == 2) ? w4.z : w4.w;
                uint4 u = *(const uint4*)src;
                float2 f0 = __half22float2(*(__half2*)&u.x);
                float2 f1 = __half22float2(*(__half2*)&u.y);
                float2 f2 = __half22float2(*(__half2*)&u.z);
                float2 f3 = __half22float2(*(__half2*)&u.w);
                acc[0] = fmaf(w, f0.x, acc[0]); acc[1] = fmaf(w, f0.y, acc[1]);
                acc[2] = fmaf(w, f1.x, acc[2]); acc[3] = fmaf(w, f1.y, acc[3]);
                acc[4] = fmaf(w, f2.x, acc[4]); acc[5] = fmaf(w, f2.y, acc[5]);
                acc[6] = fmaf(w, f3.x, acc[6]); acc[7] = fmaf(w, f3.y, acc[7]);
            }
        }
        __half2 hv[4];
#pragma unroll
        for (int k = 0; k < 4; k++)
            hv[k] = __floats2half2_rn(acc[2*k], acc[2*k+1]);
        *(uint4*)&v_sm2[p * VROW + lane * 4] = *(uint4*)hv;
    }
    __syncthreads();

    // ---- Stage 1.5: per-point channel avg / max (1 thread per point) -------
    if (t < NP) {
        const __half2* row = &v_sm2[t * VROW];
        float sum = 0.f, mx = -3.0e38f;
#pragma unroll
        for (int k = 0; k < 8; k++) {
            uint4 u = *(const uint4*)(row + k * 4);
            float2 f0 = __half22float2(*(__half2*)&u.x);
            float2 f1 = __half22float2(*(__half2*)&u.y);
            float2 f2 = __half22float2(*(__half2*)&u.z);
            float2 f3 = __half22float2(*(__half2*)&u.w);
            sum += (f0.x + f0.y) + (f1.x + f1.y) + (f2.x + f2.y) + (f3.x + f3.y);
            mx = fmaxf(mx, fmaxf(fmaxf(f0.x, f0.y), fmaxf(f1.x, f1.y)));
            mx = fmaxf(mx, fmaxf(fmaxf(f2.x, f2.y), fmaxf(f3.x, f3.y)));
        }
        savg[t] = sum * (1.0f / 64.0f);
        smax_[t] = mx;
    }
    __syncthreads();

    // ---- Stage 2: spatial attention gates ----------------------------------
    if (t < TL * 3 * 3) {
        int ra = t / 3, kw = t - ra * 3;   // interior row ra -> v-row ra+1
        float acc = __ldg(sa_b);
#pragma unroll
        for (int kh = 0; kh < 3; kh++) {
            int rr = ra + kh;
#pragma unroll
            for (int k2 = 0; k2 < 3; k2++) {
                int cc = kw + k2 - 1;
                if (cc >= 0 && cc < 3) {
                    int p = rr * 3 + cc;
                    acc += __ldg(&sa_w[kh * 3 + k2])     * savg[p]
                         + __ldg(&sa_w[9 + kh * 3 + k2]) * smax_[p];
                }
            }
        }
        m_att[t] = 1.0f + 1.0f / (1.0f + __expf(-acc));
    }
    __syncthreads();

    // ---- Stage 3: depthwise 3x3, write z to global (coalesced 256B rows) ---
    {
        int c2 = t & 31;           // half2 channel pair (2 channels)
        int lg = t >> 5;           // 0..7
        int cA = 2 * c2, cB = 2 * c2 + 1;
        float dwA[9], dwB[9];
#pragma unroll
        for (int k = 0; k < 9; k++) { dwA[k] = dw_sm[cA * 9 + k]; dwB[k] = dw_sm[cB * 9 + k]; }
        float dbA = __ldg(&dw_b[cA]), dbB = __ldg(&dw_b[cB]);
#pragma unroll
        for (int li = 0; li < 2; li++) {
            int l = lg + li * 8;
            float a0 = dbA, a1 = dbB;
#pragma unroll
            for (int kh = 0; kh < 3; kh++)
#pragma unroll
                for (int kw = 0; kw < 3; kw++) {
                    int ra = 3 * l + kh;
                    float g = m_att[ra * 3 + kw];
                    float2 v = __half22float2(v_sm2[((ra + 1) * 3 + kw) * VROW + c2]);
                    a0 = fmaf(dwA[kh * 3 + kw] * g, v.x, a0);
                    a1 = fmaf(dwB[kh * 3 + kw] * g, v.y, a1);
                }
            *(float2*)&g_z[((size_t)b * LOUT + l0 + l) * 64 + cA] = make_float2(a0, a1);
        }
    }
}

// ---------------------------------------------------------------------------
// Kernel 3: pointwise 64x64 GEMM: out[b,o,l] = sum_c pw[o,c] * z[b,l,c] + pb.
// grid: (Bsz*LOUT/64), block 256. Tile 64o x 64l, thread 4o x 4l, k-major smem.
// ---------------------------------------------------------------------------
__global__ __launch_bounds__(256) void pw_k(
    const float* __restrict__ pw_w, const float* __restrict__ pw_b,
    float* __restrict__ out)
{
    __shared__ __align__(16) float zs[64][68];   // [c][l]
    __shared__ __align__(16) float pws[64][68];  // [c][o]

    const int t   = threadIdx.x;
    const int bl0 = blockIdx.x * 64;             // flattened (b*LOUT + l) tile base
    const int b   = bl0 / LOUT;                  // tiles never cross batch
    const int lbase = bl0 - b * LOUT;

    // Load pw transposed to [c][o]
    for (int i = t * 4; i < 4096; i += 1024) {
        float4 v = *(const float4*)&pw_w[i];
        int o = i >> 6, c = i & 63;
        pws[c + 0][o] = v.x; pws[c + 1][o] = v.y;
        pws[c + 2][o] = v.z; pws[c + 3][o] = v.w;
    }
    // Load z tile transposed to [c][l]
    const float* zg = g_z + (size_t)bl0 * 64;
    for (int i = t * 4; i < 4096; i += 1024) {
        float4 v = *(const float4*)&zg[i];
        int l = i >> 6, c = i & 63;
        zs[c + 0][l] = v.x; zs[c + 1][l] = v.y;
        zs[c + 2][l] = v.z; zs[c + 3][l] = v.w;
    }
    __syncthreads();

    const int tx = t & 15, ty = t >> 4;
    const int o0 = tx * 4, lt = ty * 4;

    float acc[4][4];
#pragma unroll
    for (int i = 0; i < 4; i++) {
        float pb = __ldg(&pw_b[o0 + i]);
#pragma unroll
        for (int j = 0; j < 4; j++) acc[i][j] = pb;
    }

#pragma unroll 8
    for (int k = 0; k < 64; k++) {
        float4 a  = *(const float4*)&pws[k][o0];
        float4 zv = *(const float4*)&zs[k][lt];
        acc[0][0] = fmaf(a.x, zv.x, acc[0][0]); acc[0][1] = fmaf(a.x, zv.y, acc[0][1]);
        acc[0][2] = fmaf(a.x, zv.z, acc[0][2]); acc[0][3] = fmaf(a.x, zv.w, acc[0][3]);
        acc[1][0] = fmaf(a.y, zv.x, acc[1][0]); acc[1][1] = fmaf(a.y, zv.y, acc[1][1]);
        acc[1][2] = fmaf(a.y, zv.z, acc[1][2]); acc[1][3] = fmaf(a.y, zv.w, acc[1][3]);
        acc[2][0] = fmaf(a.z, zv.x, acc[2][0]); acc[2][1] = fmaf(a.z, zv.y, acc[2][1]);
        acc[2][2] = fmaf(a.z, zv.z, acc[2][2]); acc[2][3] = fmaf(a.z, zv.w, acc[2][3]);
        acc[3][0] = fmaf(a.w, zv.x, acc[3][0]); acc[3][1] = fmaf(a.w, zv.y, acc[3][1]);
        acc[3][2] = fmaf(a.w, zv.z, acc[3][2]); acc[3][3] = fmaf(a.w, zv.w, acc[3][3]);
    }

#pragma unroll
    for (int i = 0; i < 4; i++) {
        float4 r = make_float4(acc[i][0], acc[i][1], acc[i][2], acc[i][3]);
        *(float4*)&out[((size_t)(b * 64 + o0 + i)) * LOUT + lbase + lt] = r;
    }
}

// ---------------------------------------------------------------------------
extern "C" void kernel_launch(void* const* d_in, const int* in_sizes, int n_in,
                              void* d_out, int out_size) {
    (void)in_sizes; (void)n_in; (void)out_size;
    const float* x    = (const float*)d_in[0];
    const float* grid = (const float*)d_in[1];
    const float* sa_w = (const float*)d_in[2];
    const float* sa_b = (const float*)d_in[3];
    const float* dw_w = (const float*)d_in[4];
    const float* dw_b = (const float*)d_in[5];
    const float* pw_w = (const float*)d_in[6];
    const float* pw_b = (const float*)d_in[7];
    float* out = (float*)d_out;

    dim3 tb(32, 8);
    dim3 tg(Ww / 32, Cc / 32, Bsz * Hh);
    transpose_k<<<tg, tb>>>(x);

    dim3 sg(LOUT / TL, Bsz);
    sample_k<<<sg, 256>>>(grid, sa_w, sa_b, dw_w, dw_b);

    pw_k<<<(Bsz * LOUT) / 64, 256>>>(pw_w, pw_b, out);
}

// round 11
// speedup vs baseline: 1.1178x; 1.0196x over previous
#include <cuda_runtime.h>
#include <cuda_fp16.h>

// Problem constants
#define Bsz  2
#define Cc   64
#define Hh   128
#define Ww   256
#define HG   122880          // grid rows = L*KH
#define LOUT 40960           // output rows after stride-3 depthwise
#define TL   16              // output rows per block (sampler)
#define NR   (3*TL + 2)      // local sampled rows incl. +/-1 halo  (50)
#define NP   (NR * 3)        // local sampled points (150)
#define VROW 36              // v_sm2 row pitch in half2 (144B)

__device__ __half g_xT[Bsz * Hh * Ww * Cc];        // x as [B,H,W,C] fp16
__device__ __half g_z[Bsz * LOUT * Cc];            // depthwise output [b*l][c] fp16

// ---------------------------------------------------------------------------
// Kernel 1: NCHW fp32 -> NHWC fp16 transpose of x.
// ---------------------------------------------------------------------------
__global__ void transpose_k(const float* __restrict__ x) {
    __shared__ float tile[32][33];
    int w0 = blockIdx.x * 32;
    int c0 = blockIdx.y * 32;
    int bh = blockIdx.z;
    int b  = bh >> 7;          // H = 128
    int h  = bh & 127;
    int tx = threadIdx.x, ty = threadIdx.y;
#pragma unroll
    for (int i = 0; i < 4; i++) {
        int c = c0 + ty + i * 8;
        tile[ty + i * 8][tx] = x[((b * Cc + c) * Hh + h) * Ww + w0 + tx];
    }
    __syncthreads();
#pragma unroll
    for (int i = 0; i < 4; i++) {
        int w = w0 + ty + i * 8;
        g_xT[((size_t)(b * Hh + h) * Ww + w) * Cc + c0 + tx] =
            __float2half_rn(tile[tx][ty + i * 8]);
    }
}

// ---------------------------------------------------------------------------
// Kernel 2: grid_sample + spatial attention + depthwise(s=3) -> g_z (fp16)
// grid: (LOUT/TL, B), block 256. Branch-free clamped gather.
// ---------------------------------------------------------------------------
__global__ __launch_bounds__(256) void sample_k(
    const float* __restrict__ grid,
    const float* __restrict__ sa_w, const float* __restrict__ sa_b,
    const float* __restrict__ dw_w, const float* __restrict__ dw_b)
{
    __shared__ __align__(16) __half2 v_sm2[NP * VROW]; // 21600 B sampled vecs
    __shared__ __align__(16) float4 cw_sm[NP];         // per-tap weights (0 if OOB)
    __shared__ unsigned cxy_sm[NP];                    // packed clamped coords
    __shared__ float savg[NP];
    __shared__ float smax_[NP];
    __shared__ float m_att[TL * 3 * 3];                // (1 + sigmoid) gates
    __shared__ float dw_sm[64 * 9];

    const int t  = threadIdx.x;
    const int b  = blockIdx.y;
    const int l0 = blockIdx.x * TL;
    const __half* __restrict__ xb = g_xT + (size_t)b * (Hh * Ww * Cc);

    // ---- Stage 0: dw weights + per-point coordinate precompute -------------
    for (int i = t; i < 576; i += 256)
        dw_sm[i] = dw_w[i];

    if (t < NP) {
        float4 w4 = make_float4(0.f, 0.f, 0.f, 0.f);
        int xc0 = 0, xc1 = 0, yc0 = 0, yc1 = 0;
        int gidx = (3 * l0 - 1) * 3 + t;              // linear grid point index
        if (gidx >= 0 && gidx < HG * 3) {
            float2 g2 = __ldg((const float2*)grid + gidx);
            float gx = (g2.x + 1.0f) * 128.0f - 0.5f;   // W/2
            float gy = (g2.y + 1.0f) * 64.0f  - 0.5f;   // H/2
            float x0f = floorf(gx), y0f = floorf(gy);
            float wx = gx - x0f, wy = gy - y0f;
            int x0 = (int)x0f, y0 = (int)y0f;
            float vx0 = ((unsigned)x0       < (unsigned)Ww) ? 1.f : 0.f;
            float vx1 = ((unsigned)(x0 + 1) < (unsigned)Ww) ? 1.f : 0.f;
            float vy0 = ((unsigned)y0       < (unsigned)Hh) ? 1.f : 0.f;
            float vy1 = ((unsigned)(y0 + 1) < (unsigned)Hh) ? 1.f : 0.f;
            w4.x = (1.f - wx) * (1.f - wy) * vx0 * vy0;  // w00
            w4.y = wx * (1.f - wy)         * vx1 * vy0;  // w10
            w4.z = (1.f - wx) * wy         * vx0 * vy1;  // w01
            w4.w = wx * wy                 * vx1 * vy1;  // w11
            xc0 = min(max(x0, 0), Ww - 1);
            xc1 = min(max(x0 + 1, 0), Ww - 1);
            yc0 = min(max(y0, 0), Hh - 1);
            yc1 = min(max(y0 + 1, 0), Hh - 1);
        }
        cw_sm[t] = w4;
        cxy_sm[t] = (unsigned)xc0 | ((unsigned)xc1 << 8)
                  | ((unsigned)yc0 << 16) | ((unsigned)yc1 << 24);
    }
    __syncthreads();

    // ---- Stage 1: branch-free bilinear gather, 8 lanes/pt, 8 ch/lane -------
    const int grp  = t >> 3;      // 0..31
    const int lane = t & 7;
    const int co   = lane * 8;    // channel offset (halves)
    const __half* __restrict__ xc = xb + co;

    for (int p = grp; p < NP; p += 32) {
        float4 w4 = cw_sm[p];
        unsigned pk = cxy_sm[p];
        int xc0 = pk & 255, xc1 = (pk >> 8) & 255;
        int yc0 = (pk >> 16) & 255, yc1 = pk >> 24;
        // 4 unconditional 16B taps (weights already zeroed when invalid)
        uint4 u0 = *(const uint4*)(xc + (yc0 * Ww + xc0) * 64);
        uint4 u1 = *(const uint4*)(xc + (yc0 * Ww + xc1) * 64);
        uint4 u2 = *(const uint4*)(xc + (yc1 * Ww + xc0) * 64);
        uint4 u3 = *(const uint4*)(xc + (yc1 * Ww + xc1) * 64);

        float acc[8];
#pragma unroll
        for (int k = 0; k < 8; k++) acc[k] = 0.f;
        const uint4* us[4] = { &u0, &u1, &u2, &u3 };
        const float  ws[4] = { w4.x, w4.y, w4.z, w4.w };
#pragma unroll
        for (int tap = 0; tap < 4; tap++) {
            uint4 u = *us[tap];
            float w = ws[tap];
            float2 f0 = __half22float2(*(__half2*)&u.x);
            float2 f1 = __half22float2(*(__half2*)&u.y);
            float2 f2 = __half22float2(*(__half2*)&u.z);
            float2 f3 = __half22float2(*(__half2*)&u.w);
            acc[0] = fmaf(w, f0.x, acc[0]); acc[1] = fmaf(w, f0.y, acc[1]);
            acc[2] = fmaf(w, f1.x, acc[2]); acc[3] = fmaf(w, f1.y, acc[3]);
            acc[4] = fmaf(w, f2.x, acc[4]); acc[5] = fmaf(w, f2.y, acc[5]);
            acc[6] = fmaf(w, f3.x, acc[6]); acc[7] = fmaf(w, f3.y, acc[7]);
        }
        __half2 hv[4];
#pragma unroll
        for (int k = 0; k < 4; k++)
            hv[k] = __floats2half2_rn(acc[2*k], acc[2*k+1]);
        *(uint4*)&v_sm2[p * VROW + lane * 4] = *(uint4*)hv;
    }
    __syncthreads();

    // ---- Stage 1.5: per-point channel avg / max (1 thread per point) -------
    if (t < NP) {
        const __half2* row = &v_sm2[t * VROW];
        float sum = 0.f, mx = -3.0e38f;
#pragma unroll
        for (int k = 0; k < 8; k++) {
            uint4 u = *(const uint4*)(row + k * 4);
            float2 f0 = __half22float2(*(__half2*)&u.x);
            float2 f1 = __half22float2(*(__half2*)&u.y);
            float2 f2 = __half22float2(*(__half2*)&u.z);
            float2 f3 = __half22float2(*(__half2*)&u.w);
            sum += (f0.x + f0.y) + (f1.x + f1.y) + (f2.x + f2.y) + (f3.x + f3.y);
            mx = fmaxf(mx, fmaxf(fmaxf(f0.x, f0.y), fmaxf(f1.x, f1.y)));
            mx = fmaxf(mx, fmaxf(fmaxf(f2.x, f2.y), fmaxf(f3.x, f3.y)));
        }
        savg[t] = sum * (1.0f / 64.0f);
        smax_[t] = mx;
    }
    __syncthreads();

    // ---- Stage 2: spatial attention gates ----------------------------------
    if (t < TL * 3 * 3) {
        int ra = t / 3, kw = t - ra * 3;   // interior row ra -> v-row ra+1
        float acc = __ldg(sa_b);
#pragma unroll
        for (int kh = 0; kh < 3; kh++) {
            int rr = ra + kh;
#pragma unroll
            for (int k2 = 0; k2 < 3; k2++) {
                int cc = kw + k2 - 1;
                if (cc >= 0 && cc < 3) {
                    int p = rr * 3 + cc;
                    acc += __ldg(&sa_w[kh * 3 + k2])     * savg[p]
                         + __ldg(&sa_w[9 + kh * 3 + k2]) * smax_[p];
                }
            }
        }
        m_att[t] = 1.0f + 1.0f / (1.0f + __expf(-acc));
    }
    __syncthreads();

    // ---- Stage 3: depthwise 3x3 -> g_z (fp16, coalesced) -------------------
    {
        int c2 = t & 31;           // half2 channel pair (2 channels)
        int lg = t >> 5;           // 0..7
        int cA = 2 * c2, cB = 2 * c2 + 1;
        float dwA[9], dwB[9];
#pragma unroll
        for (int k = 0; k < 9; k++) { dwA[k] = dw_sm[cA * 9 + k]; dwB[k] = dw_sm[cB * 9 + k]; }
        float dbA = __ldg(&dw_b[cA]), dbB = __ldg(&dw_b[cB]);
#pragma unroll
        for (int li = 0; li < 2; li++) {
            int l = lg + li * 8;
            float a0 = dbA, a1 = dbB;
#pragma unroll
            for (int kh = 0; kh < 3; kh++)
#pragma unroll
                for (int kw = 0; kw < 3; kw++) {
                    int ra = 3 * l + kh;
                    float g = m_att[ra * 3 + kw];
                    float2 v = __half22float2(v_sm2[((ra + 1) * 3 + kw) * VROW + c2]);
                    a0 = fmaf(dwA[kh * 3 + kw] * g, v.x, a0);
                    a1 = fmaf(dwB[kh * 3 + kw] * g, v.y, a1);
                }
            *(__half2*)&g_z[((size_t)b * LOUT + l0 + l) * 64 + cA] =
                __floats2half2_rn(a0, a1);
        }
    }
}

// ---------------------------------------------------------------------------
// Kernel 3: pointwise 64x64 GEMM: out[b,o,l] = sum_c pw[o,c] * z[b,l,c] + pb.
// grid: (Bsz*LOUT/64), block 256. Tile 64o x 64l, thread 4o x 4l, k-major smem.
// ---------------------------------------------------------------------------
__global__ __launch_bounds__(256) void pw_k(
    const float* __restrict__ pw_w, const float* __restrict__ pw_b,
    float* __restrict__ out)
{
    __shared__ __align__(16) float zs[64][68];   // [c][l]
    __shared__ __align__(16) float pws[64][68];  // [c][o]

    const int t   = threadIdx.x;
    const int bl0 = blockIdx.x * 64;             // flattened (b*LOUT + l) tile base
    const int b   = bl0 / LOUT;                  // tiles never cross batch
    const int lbase = bl0 - b * LOUT;

    // Load pw transposed to [c][o]
    for (int i = t * 4; i < 4096; i += 1024) {
        float4 v = *(const float4*)&pw_w[i];
        int o = i >> 6, c = i & 63;
        pws[c + 0][o] = v.x; pws[c + 1][o] = v.y;
        pws[c + 2][o] = v.z; pws[c + 3][o] = v.w;
    }
    // Load z tile (fp16) transposed to [c][l] as fp32
    const __half* zg = g_z + (size_t)bl0 * 64;
    for (int i = t * 8; i < 4096; i += 2048) {
        uint4 u = *(const uint4*)&zg[i];       // 8 halves
        int l = i >> 6, c = i & 63;
        float2 f0 = __half22float2(*(__half2*)&u.x);
        float2 f1 = __half22float2(*(__half2*)&u.y);
        float2 f2 = __half22float2(*(__half2*)&u.z);
        float2 f3 = __half22float2(*(__half2*)&u.w);
        zs[c + 0][l] = f0.x; zs[c + 1][l] = f0.y;
        zs[c + 2][l] = f1.x; zs[c + 3][l] = f1.y;
        zs[c + 4][l] = f2.x; zs[c + 5][l] = f2.y;
        zs[c + 6][l] = f3.x; zs[c + 7][l] = f3.y;
    }
    __syncthreads();

    const int tx = t & 15, ty = t >> 4;
    const int o0 = tx * 4, lt = ty * 4;

    float acc[4][4];
#pragma unroll
    for (int i = 0; i < 4; i++) {
        float pb = __ldg(&pw_b[o0 + i]);
#pragma unroll
        for (int j = 0; j < 4; j++) acc[i][j] = pb;
    }

#pragma unroll 8
    for (int k = 0; k < 64; k++) {
        float4 a  = *(const float4*)&pws[k][o0];
        float4 zv = *(const float4*)&zs[k][lt];
        acc[0][0] = fmaf(a.x, zv.x, acc[0][0]); acc[0][1] = fmaf(a.x, zv.y, acc[0][1]);
        acc[0][2] = fmaf(a.x, zv.z, acc[0][2]); acc[0][3] = fmaf(a.x, zv.w, acc[0][3]);
        acc[1][0] = fmaf(a.y, zv.x, acc[1][0]); acc[1][1] = fmaf(a.y, zv.y, acc[1][1]);
        acc[1][2] = fmaf(a.y, zv.z, acc[1][2]); acc[1][3] = fmaf(a.y, zv.w, acc[1][3]);
        acc[2][0] = fmaf(a.z, zv.x, acc[2][0]); acc[2][1] = fmaf(a.z, zv.y, acc[2][1]);
        acc[2][2] = fmaf(a.z, zv.z, acc[2][2]); acc[2][3] = fmaf(a.z, zv.w, acc[2][3]);
        acc[3][0] = fmaf(a.w, zv.x, acc[3][0]); acc[3][1] = fmaf(a.w, zv.y, acc[3][1]);
        acc[3][2] = fmaf(a.w, zv.z, acc[3][2]); acc[3][3] = fmaf(a.w, zv.w, acc[3][3]);
    }

#pragma unroll
    for (int i = 0; i < 4; i++) {
        float4 r = make_float4(acc[i][0], acc[i][1], acc[i][2], acc[i][3]);
        *(float4*)&out[((size_t)(b * 64 + o0 + i)) * LOUT + lbase + lt] = r;
    }
}

// ---------------------------------------------------------------------------
extern "C" void kernel_launch(void* const* d_in, const int* in_sizes, int n_in,
                              void* d_out, int out_size) {
    (void)in_sizes; (void)n_in; (void)out_size;
    const float* x    = (const float*)d_in[0];
    const float* grid = (const float*)d_in[1];
    const float* sa_w = (const float*)d_in[2];
    const float* sa_b = (const float*)d_in[3];
    const float* dw_w = (const float*)d_in[4];
    const float* dw_b = (const float*)d_in[5];
    const float* pw_w = (const float*)d_in[6];
    const float* pw_b = (const float*)d_in[7];
    float* out = (float*)d_out;

    dim3 tb(32, 8);
    dim3 tg(Ww / 32, Cc / 32, Bsz * Hh);
    transpose_k<<<tg, tb>>>(x);

    dim3 sg(LOUT / TL, Bsz);
    sample_k<<<sg, 256>>>(grid, sa_w, sa_b, dw_w, dw_b);

    pw_k<<<(Bsz * LOUT) / 64, 256>>>(pw_w, pw_b, out);
}